// round 11
// baseline (speedup 1.0000x reference)
#include <cuda_runtime.h>
#include <cuda_bf16.h>
#include <cstdint>

// ---------------- problem constants ----------------
#define NS      512
#define KSEG    16
#define SEGD    8192
#define FSTRIDE (KSEG * SEGD)
#define OP_SCALE 1.1952286093343936f   // 1/sqrt(0.7) folded per operand
#define NCLASS  10

// ---------------- GEMM config ----------------
#define MT      64                     // class tile
#define CK      64                     // bf16 cols per chunk (128B rows, SW128)
#define KSPLIT  4
#define KQ      (SEGD / KSPLIT)        // 2048
#define CHPU    (KQ / CK)              // 32 chunks per unit
#define OP_BYTES    (MT * 128)         // 8192 per operand per stage
#define STAGE_BYTES (2 * OP_BYTES)     // 16384 (A + B)
#define NSTG    2

#define NROWPAD 640                    // grouped rows padded
#define MAXP    32                     // max class tile-pairs
#define NPL     (KSEG * KSPLIT)        // 64 gram planes

// ---------------- device scratch ----------------
__device__ float g_gram[(size_t)NPL * MAXP * MT * MT];  // 33.5 MB partials
__device__ float g_partials[2048];
__device__ int   g_red_count;
// schedule (rebuilt by prep every launch; deterministic)
__device__ int   g_rowsrc[NROWPAD];    // grouped row -> original sample (pad->0)
__device__ int   g_cnum[NCLASS], g_cT[NCLASS], g_cpbase[NCLASS];
__device__ int   g_pairM[MAXP], g_pairN[MAXP];
__device__ int   g_P;

// ---------------- helpers ----------------
__device__ __forceinline__ uint32_t smem_u32(const void* p) {
    uint32_t a;
    asm("{ .reg .u64 t; cvta.to.shared.u64 t, %1; cvt.u32.u64 %0, t; }" : "=r"(a) : "l"(p));
    return a;
}
#define SW128(o) ((o) ^ (((o) >> 3) & 0x70))

__device__ __forceinline__ void ldsm_x4(uint32_t& r0, uint32_t& r1, uint32_t& r2, uint32_t& r3,
                                        uint32_t addr) {
    asm volatile("ldmatrix.sync.aligned.m8n8.x4.shared.b16 {%0,%1,%2,%3}, [%4];"
                 : "=r"(r0), "=r"(r1), "=r"(r2), "=r"(r3) : "r"(addr));
}
__device__ __forceinline__ void mma16816(float* c, const uint32_t* a, uint32_t b0, uint32_t b1) {
    asm volatile(
        "mma.sync.aligned.m16n8k16.row.col.f32.bf16.bf16.f32 "
        "{%0,%1,%2,%3}, {%4,%5,%6,%7}, {%8,%9}, {%0,%1,%2,%3};"
        : "+f"(c[0]), "+f"(c[1]), "+f"(c[2]), "+f"(c[3])
        : "r"(a[0]), "r"(a[1]), "r"(a[2]), "r"(a[3]), "r"(b0), "r"(b1));
}
// 8 scaled f32 -> uint4 of bf16x2
__device__ __forceinline__ uint4 cvt8(const float4& a, const float4& b) {
    __nv_bfloat162 h0 = __floats2bfloat162_rn(a.x * OP_SCALE, a.y * OP_SCALE);
    __nv_bfloat162 h1 = __floats2bfloat162_rn(a.z * OP_SCALE, a.w * OP_SCALE);
    __nv_bfloat162 h2 = __floats2bfloat162_rn(b.x * OP_SCALE, b.y * OP_SCALE);
    __nv_bfloat162 h3 = __floats2bfloat162_rn(b.z * OP_SCALE, b.w * OP_SCALE);
    uint4 v;
    v.x = *(uint32_t*)&h0; v.y = *(uint32_t*)&h1;
    v.z = *(uint32_t*)&h2; v.w = *(uint32_t*)&h3;
    return v;
}

// ---------------------------------------------------------------------------
// Prep (1 block, 512 threads, ~2.5us): label dtype detect; stable grouping
// rank via __match_any_sync + per-warp class histograms; tile-pair schedule.
// Fully deterministic.
// ---------------------------------------------------------------------------
__global__ void prep_kernel(const int* __restrict__ lab) {
    __shared__ int wcnt[16][NCLASS];
    __shared__ int cnt[NCLASS], cstart[NCLASS];
    const int t = threadIdx.x;
    const int lane = t & 31, w = t >> 5;

    // int32 vs int64: labels 0..9 -> odd 32-bit words all zero iff int64
    int viol = (lab[2 * t + 1] != 0) ? 1 : 0;
    int is32 = __syncthreads_or(viol);
    const int v = is32 ? lab[t] : lab[2 * t];

    if (t < 16 * NCLASS) ((int*)wcnt)[t] = 0;
    g_rowsrc[t] = 0;
    if (t < NROWPAD - NS) g_rowsrc[NS + t] = 0;
    __syncthreads();

    const unsigned m = __match_any_sync(0xffffffffu, v);
    const int riw = __popc(m & ((1u << lane) - 1));       // rank within warp
    if (lane == (__ffs(m) - 1)) wcnt[w][v] = __popc(m);
    __syncthreads();

    int rank = riw;
    for (int ww = 0; ww < w; ww++) rank += wcnt[ww][v];

    if (t < NCLASS) {
        int s = 0;
        for (int ww = 0; ww < 16; ww++) s += wcnt[ww][t];
        cnt[t] = s;
    }
    __syncthreads();

    if (t == 0) {
        int start = 0, P = 0;
        for (int c = 0; c < NCLASS; c++) {
            const int n = cnt[c];
            cstart[c] = start;
            g_cnum[c] = n;
            const int T = (n + MT - 1) / MT;
            g_cT[c] = T;
            g_cpbase[c] = P;
            for (int ti = 0; ti < T; ti++)
                for (int tj = ti; tj < T; tj++) {
                    if (P < MAXP) { g_pairM[P] = start + MT * ti; g_pairN[P] = start + MT * tj; }
                    P++;
                }
            start += n;
        }
        g_P = (P > MAXP) ? MAXP : P;
    }
    __syncthreads();
    g_rowsrc[cstart[v] + rank] = t;    // grouped row -> original sample
}

// ---------------------------------------------------------------------------
// Fused convert + block-diagonal Gram GEMM. Grid (MAXP, KSEG, KSPLIT);
// pidx >= g_P exits. 192 threads:
//   warps 0-3 (128 thr): LDSM/HMMA consumers, 2x2 grid of 32x32 tiles.
//   warps 4-5 (64 thr) : producers — LDG f32 rows (gathered via g_rowsrc),
//                        cvt->bf16 (scale folded), STS SW128.
// 2-stage smem double buffer, whole-CTA __syncthreads handshake (2/chunk).
// Producer LDGs for chunk c+1 issue under consumers' MMA of chunk c.
// Feature data is read from HBM exactly ONCE (no bf16 intermediate).
// ---------------------------------------------------------------------------
__global__ void __launch_bounds__(192)
gemm_kernel(const float* __restrict__ F) {
    const int pidx = blockIdx.x;
    if (pidx >= g_P) return;
    const int seg = blockIdx.y;
    const int kq  = blockIdx.z;

    __shared__ __align__(1024) char smem[NSTG * STAGE_BYTES];  // 32 KB
    const uint32_t sbase = smem_u32(smem);

    const int tid = threadIdx.x;
    const int Moff = g_pairM[pidx];
    const int Noff = g_pairN[pidx];
    const bool diag = (Moff == Noff);

    if (tid >= 128) {
        // -------- producers: one tile row per thread --------
        const int p = tid - 128;                 // 0..63
        const size_t kbase = (size_t)seg * SEGD + (size_t)kq * KQ;
        const float* __restrict__ srcA =
            F + (size_t)g_rowsrc[Moff + p] * FSTRIDE + kbase;
        const float* __restrict__ srcB =
            F + (size_t)g_rowsrc[Noff + p] * FSTRIDE + kbase;
        const uint32_t rowoff = (uint32_t)(p * 128);

        float4 v[16];
        auto ldg16 = [&](const float* s) {
            const float4* q4 = (const float4*)s;
#pragma unroll
            for (int q = 0; q < 16; q++) v[q] = q4[q];
        };
        auto sts_row = [&](uint32_t dst) {
#pragma unroll
            for (int q = 0; q < 8; q++)
                *(uint4*)(smem + (dst - sbase) + SW128(rowoff + q * 16)) =
                    cvt8(v[2 * q], v[2 * q + 1]);
        };

        // prologue: fill stage 0 with chunk 0
        ldg16(srcA);
        sts_row(sbase);
        if (!diag) { ldg16(srcB); sts_row(sbase + OP_BYTES); }
        __syncthreads();                          // stage 0 full

        for (int c = 0; c < CHPU; c++) {
            if (c + 1 < CHPU) ldg16(srcA + (c + 1) * CK);   // overlaps MMA(c)
            __syncthreads();                      // consumers done MMA(c)
            if (c + 1 < CHPU) {
                const uint32_t st = sbase + ((c + 1) & 1) * STAGE_BYTES;
                sts_row(st);
                if (!diag) {                      // rare path: exposed latency ok
                    ldg16(srcB + (c + 1) * CK);
                    sts_row(st + OP_BYTES);
                }
            }
            __syncthreads();                      // stage (c+1) full
        }
        return;
    }

    // -------- consumers: 4 warps, 2x2 grid of 32x32 tiles --------
    const int lane = tid & 31;
    const int wid  = tid >> 5;
    const int wm   = wid & 1;
    const int wn   = wid >> 1;
    const int lrow = lane & 15;
    const int khf  = (lane >> 4) & 1;
    const int gid  = lane >> 2, tig = lane & 3;

    float acc[2][4][4];
#pragma unroll
    for (int i = 0; i < 2; i++)
#pragma unroll
        for (int j = 0; j < 4; j++)
#pragma unroll
            for (int q = 0; q < 4; q++) acc[i][j][q] = 0.0f;

    __syncthreads();                              // stage 0 full

    for (int c = 0; c < CHPU; c++) {
        const uint32_t sa = sbase + (c & 1) * STAGE_BYTES;
        const uint32_t sb = diag ? sa : (sa + OP_BYTES);
#pragma unroll
        for (int ks = 0; ks < 4; ks++) {
            const int kb = ks * 32 + khf * 16;
            uint32_t a[2][4], bf[2][4];
#pragma unroll
            for (int im = 0; im < 2; im++) {
                int row = wm * 32 + im * 16 + lrow;
                ldsm_x4(a[im][0], a[im][1], a[im][2], a[im][3],
                        sa + SW128(row * 128 + kb));
            }
#pragma unroll
            for (int j2 = 0; j2 < 2; j2++) {
                int row = wn * 32 + j2 * 16 + lrow;
                ldsm_x4(bf[j2][0], bf[j2][1], bf[j2][2], bf[j2][3],
                        sb + SW128(row * 128 + kb));
            }
#pragma unroll
            for (int im = 0; im < 2; im++)
#pragma unroll
                for (int jn = 0; jn < 4; jn++)
                    mma16816(acc[im][jn], a[im],
                             bf[jn >> 1][jn & 1], bf[jn >> 1][2 + (jn & 1)]);
        }
        __syncthreads();                          // MMA(c) done
        __syncthreads();                          // stage (c+1) full
    }

    float* Cb = g_gram + ((size_t)(seg * KSPLIT + kq) * MAXP + pidx) * (MT * MT);
#pragma unroll
    for (int im = 0; im < 2; im++) {
#pragma unroll
        for (int jn = 0; jn < 4; jn++) {
            int r0 = wm * 32 + im * 16 + gid;
            int c0 = wn * 32 + jn * 8 + tig * 2;
            *(float2*)&Cb[r0 * MT + c0] =
                make_float2(acc[im][jn][0], acc[im][jn][1]);
            *(float2*)&Cb[(r0 + 8) * MT + c0] =
                make_float2(acc[im][jn][2], acc[im][jn][3]);
        }
    }
}

// ---------------------------------------------------------------------------
// Loss over within-class pairs only (i < j, weight 2). Sums 4 K-partials,
// top-4-of-16 exp ratio; deterministic tree reduce; last block writes mean.
// Grid: NCLASS x 64 blocks (i, j in [0,128) per class); inactive threads
// skip the gram loads via the i<j<nc guard.
// ---------------------------------------------------------------------------
__global__ __launch_bounds__(256) void reduce_kernel(float* __restrict__ out) {
    const int t     = threadIdx.x;
    const int c     = blockIdx.x >> 6;
    const int local = ((blockIdx.x & 63) << 8) + t;
    const int i = local >> 7;
    const int j = local & 127;

    float loss = 0.0f;
    const int nc = g_cnum[c];
    if (i < j && j < nc) {
        const int T  = g_cT[c];
        const int ti = i >> 6, tj = j >> 6;
        const int pidx = g_cpbase[c] + ti * T - (ti * (ti - 1)) / 2 + (tj - ti);
        const int cell = (i & 63) * MT + (j & 63);

        float v[KSEG];
        float m = -1e30f;
#pragma unroll
        for (int k = 0; k < KSEG; k++) {
            float s = 0.0f;
#pragma unroll
            for (int kq = 0; kq < KSPLIT; kq++)
                s += g_gram[((size_t)(k * KSPLIT + kq) * MAXP + pidx) * (MT * MT) + cell];
            v[k] = s;
            m = fmaxf(m, s);
        }
        float tot = 0.0f, t0 = 0.0f, t1 = 0.0f, t2 = 0.0f, t3 = 0.0f;
#pragma unroll
        for (int k = 0; k < KSEG; k++) {
            const float e = __expf(v[k] - m);
            tot += e;
            if (e > t0)      { t3 = t2; t2 = t1; t1 = t0; t0 = e; }
            else if (e > t1) { t3 = t2; t2 = t1; t1 = e; }
            else if (e > t2) { t3 = t2; t2 = e; }
            else if (e > t3) { t3 = e; }
        }
        loss = -2.0f * __logf((t0 + t1 + t2 + t3) / tot);   // both (a,b),(b,a)
    }

    __shared__ float red[256];
    red[t] = loss;
    __syncthreads();
#pragma unroll
    for (int s = 128; s > 0; s >>= 1) {
        if (t < s) red[t] += red[t + s];
        __syncthreads();
    }

    __shared__ int isLast;
    if (t == 0) {
        g_partials[blockIdx.x] = red[0];
        __threadfence();
        int cn = atomicAdd(&g_red_count, 1);
        isLast = (cn == gridDim.x - 1);
    }
    __syncthreads();

    if (isLast) {
        float s = __ldcg(&g_partials[t]) + __ldcg(&g_partials[t + 256]);
        if (t + 512 < 640) s += __ldcg(&g_partials[t + 512]);
        red[t] = s;
        __syncthreads();
#pragma unroll
        for (int sh = 128; sh > 0; sh >>= 1) {
            if (t < sh) red[t] += red[t + sh];
            __syncthreads();
        }
        if (t == 0) {
            out[0] = red[0] / (float)(NS * NS);
            g_red_count = 0;           // reset for graph replay
        }
    }
}

// ---------------------------------------------------------------------------
extern "C" void kernel_launch(void* const* d_in, const int* in_sizes, int n_in,
                              void* d_out, int out_size) {
    const float* features = (const float*)d_in[0];
    const int*   labels   = (const int*)d_in[1];
    (void)in_sizes; (void)n_in; (void)out_size;

    prep_kernel<<<1, NS>>>(labels);
    dim3 grid(MAXP, KSEG, KSPLIT);     // inactive pairs exit on g_P
    gemm_kernel<<<grid, 192>>>(features);
    reduce_kernel<<<NCLASS * 64, 256>>>((float*)d_out);
}

// round 13
// speedup vs baseline: 1.5092x; 1.5092x over previous
#include <cuda_runtime.h>
#include <cuda_bf16.h>
#include <cstdint>

// ---------------- problem constants ----------------
#define NS      512
#define KSEG    16
#define SEGD    8192
#define FSTRIDE (KSEG * SEGD)
#define TEMP_INV (1.0f / 0.7f)        // applied once in epilogue (exact fold)
#define NCLASS  10

// ---------------- GEMM config ----------------
#define MT      64                     // class tile
#define CKF     32                     // f32 per chunk row (128B rows, SW128)
#define KSPLIT  4
#define KQ      (SEGD / KSPLIT)        // 2048
#define CHPU    (KQ / CKF)             // 64 chunks per unit
#define STAGES  3
#define OP_BYTES    (MT * 128)         // 8192 per operand per stage
#define STAGE_BYTES (2 * OP_BYTES)     // 16384
// static smem: 3 * 16384 = 48 KB -> 4 CTAs/SM

#define NROWPAD 640
#define MAXP    32
#define NPL     (KSEG * KSPLIT)        // 64 gram planes

// ---------------- device scratch ----------------
__device__ float g_gram[(size_t)NPL * MAXP * MT * MT];  // 33.5 MB partials
__device__ float g_partials[2048];
__device__ int   g_red_count;
// schedule (rebuilt by prep every launch; deterministic)
__device__ int   g_rowsrc[NROWPAD];    // grouped row -> original sample (pad->0)
__device__ int   g_cnum[NCLASS], g_cT[NCLASS], g_cpbase[NCLASS];
__device__ int   g_pairM[MAXP], g_pairN[MAXP];
__device__ int   g_P;

// ---------------- helpers ----------------
__device__ __forceinline__ uint32_t smem_u32(const void* p) {
    uint32_t a;
    asm("{ .reg .u64 t; cvta.to.shared.u64 t, %1; cvt.u32.u64 %0, t; }" : "=r"(a) : "l"(p));
    return a;
}
#define CP16(dst, src) \
    asm volatile("cp.async.cg.shared.global [%0], [%1], 16;" :: "r"(dst), "l"(src))
#define CP_COMMIT() asm volatile("cp.async.commit_group;" ::: "memory")
template <int N> __device__ __forceinline__ void cp_wait() {
    asm volatile("cp.async.wait_group %0;" :: "n"(N) : "memory");
}
#define SW128(o) ((o) ^ (((o) >> 3) & 0x70))

__device__ __forceinline__ float2 lds64(uint32_t addr) {
    float2 v;
    asm volatile("ld.shared.v2.f32 {%0,%1}, [%2];" : "=f"(v.x), "=f"(v.y) : "r"(addr));
    return v;
}
// pack 2 k-consecutive f32 -> bf16x2 fragment reg (lo = first element)
__device__ __forceinline__ uint32_t cvt_pair(float2 v) {
    uint32_t d;
    asm("cvt.rn.bf16x2.f32 %0, %1, %2;" : "=r"(d) : "f"(v.y), "f"(v.x));
    return d;
}
__device__ __forceinline__ void mma16816(float* c, const uint32_t* a, uint32_t b0, uint32_t b1) {
    asm volatile(
        "mma.sync.aligned.m16n8k16.row.col.f32.bf16.bf16.f32 "
        "{%0,%1,%2,%3}, {%4,%5,%6,%7}, {%8,%9}, {%0,%1,%2,%3};"
        : "+f"(c[0]), "+f"(c[1]), "+f"(c[2]), "+f"(c[3])
        : "r"(a[0]), "r"(a[1]), "r"(a[2]), "r"(a[3]), "r"(b0), "r"(b1));
}

// ---------------------------------------------------------------------------
// Prep (1 block, 512 threads): label dtype detect; stable grouping rank via
// __match_any_sync + per-warp class histograms; tile-pair schedule.
// ---------------------------------------------------------------------------
__global__ void prep_kernel(const int* __restrict__ lab) {
    __shared__ int wcnt[16][NCLASS];
    __shared__ int cnt[NCLASS], cstart[NCLASS];
    const int t = threadIdx.x;
    const int lane = t & 31, w = t >> 5;

    // int32 vs int64: labels 0..9 -> odd 32-bit words all zero iff int64
    int viol = (lab[2 * t + 1] != 0) ? 1 : 0;
    int is32 = __syncthreads_or(viol);
    const int v = is32 ? lab[t] : lab[2 * t];

    if (t < 16 * NCLASS) ((int*)wcnt)[t] = 0;
    g_rowsrc[t] = 0;
    if (t < NROWPAD - NS) g_rowsrc[NS + t] = 0;
    __syncthreads();

    const unsigned m = __match_any_sync(0xffffffffu, v);
    const int riw = __popc(m & ((1u << lane) - 1));
    if (lane == (__ffs(m) - 1)) wcnt[w][v] = __popc(m);
    __syncthreads();

    int rank = riw;
    for (int ww = 0; ww < w; ww++) rank += wcnt[ww][v];

    if (t < NCLASS) {
        int s = 0;
        for (int ww = 0; ww < 16; ww++) s += wcnt[ww][t];
        cnt[t] = s;
    }
    __syncthreads();

    if (t == 0) {
        int start = 0, P = 0;
        for (int c = 0; c < NCLASS; c++) {
            const int n = cnt[c];
            cstart[c] = start;
            g_cnum[c] = n;
            const int T = (n + MT - 1) / MT;
            g_cT[c] = T;
            g_cpbase[c] = P;
            for (int ti = 0; ti < T; ti++)
                for (int tj = ti; tj < T; tj++) {
                    if (P < MAXP) { g_pairM[P] = start + MT * ti; g_pairN[P] = start + MT * tj; }
                    P++;
                }
            start += n;
        }
        g_P = (P > MAXP) ? MAXP : P;
    }
    __syncthreads();
    g_rowsrc[cstart[v] + rank] = t;
}

// ---------------------------------------------------------------------------
// Fused block-diagonal Gram GEMM on raw f32 (single HBM read of features).
// Grid (MAXP, KSEG, KSPLIT); pidx >= g_P exits. 128 threads, no warp
// specialization: all warps cp.async the f32 chunk (3-stage, SW128-swizzled
// 128B rows) AND compute. Fragments built by LDS.64 + cvt.rn.bf16x2.f32 per
// the PTX m16n8k16 layout; 1/T folded once in the epilogue.
// Pipeline: prefetch depth 2 (stage (c+2)%3 never aliases stage c%3 in use).
// ---------------------------------------------------------------------------
__global__ void __launch_bounds__(128)
gemm_kernel(const float* __restrict__ F) {
    const int pidx = blockIdx.x;
    if (pidx >= g_P) return;
    const int seg = blockIdx.y;
    const int kq  = blockIdx.z;

    __shared__ __align__(1024) char smem[STAGES * STAGE_BYTES];  // 48 KB
    const uint32_t sbase = smem_u32(smem);

    const int tid  = threadIdx.x;
    const int lane = tid & 31;
    const int wid  = tid >> 5;
    const int wm   = wid & 1;            // 2 warps along M
    const int wn   = wid >> 1;           // 2 warps along N
    const int g    = lane >> 2;          // group id 0..7
    const int ctid = lane & 3;
    const int tig  = lane & 3;

    const int Moff = g_pairM[pidx];
    const int Noff = g_pairN[pidx];
    const bool diag = (Moff == Noff);

    // per-thread cp.async source pointers / dest offsets (4 x 16B per operand)
    const size_t kbase = (size_t)seg * SEGD + (size_t)kq * KQ;
    const float* aptr[4];
    const float* bptr[4];
    uint32_t dsto[4];
#pragma unroll
    for (int i = 0; i < 4; i++) {
        const int q = i * 128 + tid;
        const int row = q >> 3, u = q & 7;      // 64 rows x 8 16B-units
        aptr[i] = F + (size_t)g_rowsrc[Moff + row] * FSTRIDE + kbase + u * 4;
        bptr[i] = F + (size_t)g_rowsrc[Noff + row] * FSTRIDE + kbase + u * 4;
        dsto[i] = SW128((uint32_t)(row * 128 + u * 16));
    }

    auto load_chunk = [&](int c) {
        const uint32_t st = sbase + (c % STAGES) * STAGE_BYTES;
        const int koff = c * CKF;
#pragma unroll
        for (int i = 0; i < 4; i++)
            CP16(st + dsto[i], aptr[i] + koff);
        if (!diag) {
#pragma unroll
            for (int i = 0; i < 4; i++)
                CP16(st + OP_BYTES + dsto[i], bptr[i] + koff);
        }
        CP_COMMIT();
    };

    float acc[2][4][4];
#pragma unroll
    for (int i = 0; i < 2; i++)
#pragma unroll
        for (int j = 0; j < 4; j++)
#pragma unroll
            for (int q = 0; q < 4; q++) acc[i][j][q] = 0.0f;

    auto compute = [&](int cs) {                  // cs = stage index (wrapped!)
        const uint32_t sa = sbase + cs * STAGE_BYTES;
        const uint32_t sb = diag ? sa : (sa + OP_BYTES);
#pragma unroll
        for (int ks = 0; ks < 2; ks++) {          // 2 x k16 per 32-f32 chunk
            uint32_t a[2][4], bf[4][2];
#pragma unroll
            for (int im = 0; im < 2; im++) {
#pragma unroll
                for (int r = 0; r < 4; r++) {
                    const int row  = wm * 32 + im * 16 + g + (r & 1) * 8;
                    const int kcol = ks * 16 + (r >> 1) * 8 + ctid * 2;
                    a[im][r] = cvt_pair(lds64(sa + SW128((uint32_t)(row * 128 + kcol * 4))));
                }
            }
#pragma unroll
            for (int nb = 0; nb < 4; nb++) {
#pragma unroll
                for (int r = 0; r < 2; r++) {
                    const int row  = wn * 32 + nb * 8 + g;
                    const int kcol = ks * 16 + r * 8 + ctid * 2;
                    bf[nb][r] = cvt_pair(lds64(sb + SW128((uint32_t)(row * 128 + kcol * 4))));
                }
            }
#pragma unroll
            for (int im = 0; im < 2; im++)
#pragma unroll
                for (int nb = 0; nb < 4; nb++)
                    mma16816(acc[im][nb], a[im], bf[nb][0], bf[nb][1]);
        }
    };

    load_chunk(0);
    load_chunk(1);
    for (int c = 0; c < CHPU; c++) {
        cp_wait<1>();
        __syncthreads();
        compute(c % STAGES);                      // FIX: wrapped stage index
        if (c + 2 < CHPU) load_chunk(c + 2);
        else CP_COMMIT();                 // empty group keeps wait<1> semantics
    }

    float* Cb = g_gram + ((size_t)(seg * KSPLIT + kq) * MAXP + pidx) * (MT * MT);
    const int gid = lane >> 2;
#pragma unroll
    for (int im = 0; im < 2; im++) {
#pragma unroll
        for (int nb = 0; nb < 4; nb++) {
            const int r0 = wm * 32 + im * 16 + gid;
            const int c0 = wn * 32 + nb * 8 + tig * 2;
            *(float2*)&Cb[r0 * MT + c0] =
                make_float2(acc[im][nb][0] * TEMP_INV, acc[im][nb][1] * TEMP_INV);
            *(float2*)&Cb[(r0 + 8) * MT + c0] =
                make_float2(acc[im][nb][2] * TEMP_INV, acc[im][nb][3] * TEMP_INV);
        }
    }
}

// ---------------------------------------------------------------------------
// Loss over within-class pairs only (i < j, weight 2). Sums 4 K-partials,
// top-4-of-16 exp ratio; deterministic tree reduce; last block writes mean.
// ---------------------------------------------------------------------------
__global__ __launch_bounds__(256) void reduce_kernel(float* __restrict__ out) {
    const int t     = threadIdx.x;
    const int c     = blockIdx.x >> 6;
    const int local = ((blockIdx.x & 63) << 8) + t;
    const int i = local >> 7;
    const int j = local & 127;

    float loss = 0.0f;
    const int nc = g_cnum[c];
    if (i < j && j < nc) {
        const int T  = g_cT[c];
        const int ti = i >> 6, tj = j >> 6;
        const int pidx = g_cpbase[c] + ti * T - (ti * (ti - 1)) / 2 + (tj - ti);
        const int cell = (i & 63) * MT + (j & 63);

        float v[KSEG];
        float m = -1e30f;
#pragma unroll
        for (int k = 0; k < KSEG; k++) {
            float s = 0.0f;
#pragma unroll
            for (int kq = 0; kq < KSPLIT; kq++)
                s += g_gram[((size_t)(k * KSPLIT + kq) * MAXP + pidx) * (MT * MT) + cell];
            v[k] = s;
            m = fmaxf(m, s);
        }
        float tot = 0.0f, t0 = 0.0f, t1 = 0.0f, t2 = 0.0f, t3 = 0.0f;
#pragma unroll
        for (int k = 0; k < KSEG; k++) {
            const float e = __expf(v[k] - m);
            tot += e;
            if (e > t0)      { t3 = t2; t2 = t1; t1 = t0; t0 = e; }
            else if (e > t1) { t3 = t2; t2 = t1; t1 = e; }
            else if (e > t2) { t3 = t2; t2 = e; }
            else if (e > t3) { t3 = e; }
        }
        loss = -2.0f * __logf((t0 + t1 + t2 + t3) / tot);   // both (a,b),(b,a)
    }

    __shared__ float red[256];
    red[t] = loss;
    __syncthreads();
#pragma unroll
    for (int s = 128; s > 0; s >>= 1) {
        if (t < s) red[t] += red[t + s];
        __syncthreads();
    }

    __shared__ int isLast;
    if (t == 0) {
        g_partials[blockIdx.x] = red[0];
        __threadfence();
        int cn = atomicAdd(&g_red_count, 1);
        isLast = (cn == gridDim.x - 1);
    }
    __syncthreads();

    if (isLast) {
        float s = __ldcg(&g_partials[t]) + __ldcg(&g_partials[t + 256]);
        if (t + 512 < 640) s += __ldcg(&g_partials[t + 512]);
        red[t] = s;
        __syncthreads();
#pragma unroll
        for (int sh = 128; sh > 0; sh >>= 1) {
            if (t < sh) red[t] += red[t + sh];
            __syncthreads();
        }
        if (t == 0) {
            out[0] = red[0] / (float)(NS * NS);
            g_red_count = 0;           // reset for graph replay
        }
    }
}

// ---------------------------------------------------------------------------
extern "C" void kernel_launch(void* const* d_in, const int* in_sizes, int n_in,
                              void* d_out, int out_size) {
    const float* features = (const float*)d_in[0];
    const int*   labels   = (const int*)d_in[1];
    (void)in_sizes; (void)n_in; (void)out_size;

    prep_kernel<<<1, NS>>>(labels);
    dim3 grid(MAXP, KSEG, KSPLIT);     // inactive pairs exit on g_P
    gemm_kernel<<<grid, 128>>>(features);
    reduce_kernel<<<NCLASS * 64, 256>>>((float*)d_out);
}